// round 2
// baseline (speedup 1.0000x reference)
#include <cuda_runtime.h>

#define FULLMASK 0xffffffffu
#define NTAGS 32
#define BOS_IDX 30
#define EOS_IDX 31
#define L2E 1.4426950408889634f
#define LN2 0.6931471805599453f

typedef unsigned long long ull;

static __device__ __forceinline__ ull pack2(float x, float y) {
    ull r;
    asm("mov.b64 %0, {%1,%2};" : "=l"(r) : "f"(x), "f"(y));
    return r;
}
static __device__ __forceinline__ void ffma2(ull& d, ull a, ull b) {
    asm("fma.rn.f32x2 %0, %1, %2, %0;" : "+l"(d) : "l"(a), "l"(b));
}
static __device__ __forceinline__ ull add2(ull a, ull b) {
    ull r;
    asm("add.rn.f32x2 %0, %1, %2;" : "=l"(r) : "l"(a), "l"(b));
    return r;
}
static __device__ __forceinline__ void unpack2(ull v, float& x, float& y) {
    asm("mov.b64 {%0,%1}, %2;" : "=f"(x), "=f"(y) : "l"(v));
}
static __device__ __forceinline__ float ex2_(float x) {
    float r;
    asm("ex2.approx.f32 %0, %1;" : "=f"(r) : "f"(x));
    return r;
}
static __device__ __forceinline__ float lg2_(float x) {
    float r;
    asm("lg2.approx.f32 %0, %1;" : "=f"(r) : "f"(x));
    return r;
}

// One warp per sequence, lane j owns tag j.
// Multiplicative recurrence in log2 domain:
//   beta_t = exp2(alpha_t*log2e - C_t)
//   s_j    = sum_i E[j,i] * beta_i           (E = exp(transitions), constant)
//   beta'  = s * K,  K = ex2(em*log2e - D),  D = lg2(s_EOS of previous step)
//   C     += D  (scalar, accumulated; alpha materialized only at the end)
// The only on-chain ops per step: FMUL, STS, syncwarp, LDS, FFMA2 tree.
__global__ __launch_bounds__(64) void crf_forward_kernel(
    const float* __restrict__ emission,   // [B, T, 32]
    const float* __restrict__ trans,      // [32, 32]
    float* __restrict__ out,              // [B]
    int B, int T)
{
    const int lane = threadIdx.x & 31;
    const int w    = threadIdx.x >> 5;
    const int b    = blockIdx.x * 2 + w;

    __shared__ float sbeta[2][2][NTAGS];  // [warp][double-buffer][tag]

    if (b >= B) return;  // warp-uniform (B even)

    // one-time: E row for this lane (exp of transitions), packed f32x2
    ull er[16];
    {
        const float* trow = trans + lane * NTAGS;
        #pragma unroll
        for (int q = 0; q < 16; q++)
            er[q] = pack2(expf(trow[2 * q]), expf(trow[2 * q + 1]));
    }

    const float* em = emission + (size_t)b * T * NTAGS + lane;

    // step 0 (analytic: only BOS survives init alpha), convert to log2 units
    float a2 = (em[0] + trans[lane * NTAGS + BOS_IDX]) * L2E;
    float Csum = __shfl_sync(FULLMASK, a2, EOS_IDX);
    float beta = ex2_(a2 - Csum);   // exp2(-1443-...) = 0 on dead BOS lane
    float sEOSp = 1.0f;             // => D = 0 for first iteration

    // emission prefetch ring, depth 4 (raw values; log2e folded later)
    float e0 = em[(size_t)(1 < T ? 1 : T - 1) * NTAGS];
    float e1 = em[(size_t)(2 < T ? 2 : T - 1) * NTAGS];
    float e2 = em[(size_t)(3 < T ? 3 : T - 1) * NTAGS];
    float e3 = em[(size_t)(4 < T ? 4 : T - 1) * NTAGS];

    #pragma unroll 4
    for (int t = 1; t < T; ++t) {
        float emv = e0;
        e0 = e1; e1 = e2; e2 = e3;
        int tp = (t + 4 < T) ? (t + 4) : (T - 1);
        e3 = em[(size_t)tp * NTAGS];

        // off-chain: rescale constant from previous step's s_EOS (lag-1)
        float D = lg2_(sEOSp);
        Csum += D;
        float K = ex2_(fmaf(emv, L2E, -D));

        // exchange betas (double-buffered, one syncwarp per step)
        float* sb = sbeta[w][t & 1];
        sb[lane] = beta;
        __syncwarp();

        // matvec: s_j = sum_i E[j,i] * beta_i, 16 packed FMAs, 4 accumulators
        const float4* bp = (const float4*)sb;
        ull sA = 0ull, sB = 0ull, sC = 0ull, sD = 0ull;
        #pragma unroll
        for (int q = 0; q < 4; q++) {
            float4 u = bp[2 * q];
            float4 v = bp[2 * q + 1];
            ffma2(sA, er[4 * q + 0], pack2(u.x, u.y));
            ffma2(sB, er[4 * q + 1], pack2(u.z, u.w));
            ffma2(sC, er[4 * q + 2], pack2(v.x, v.y));
            ffma2(sD, er[4 * q + 3], pack2(v.z, v.w));
        }
        ull sT = add2(add2(sA, sB), add2(sC, sD));
        float sx, sy;
        unpack2(sT, sx, sy);
        float s = sx + sy;

        sEOSp = __shfl_sync(FULLMASK, s, EOS_IDX);  // consumed next iter
        beta = s * K;                               // the only on-chain math
    }

    // materialize alpha (log2 units) and do terminal lse over the warp
    float ahat = lg2_(beta) + Csum;                     // -inf on BOS lane: ok
    float v = fmaf(trans[EOS_IDX * NTAGS + lane], L2E, ahat);
    float mm = v;
    #pragma unroll
    for (int o = 16; o; o >>= 1)
        mm = fmaxf(mm, __shfl_xor_sync(FULLMASK, mm, o));
    float ex = ex2_(v - mm);
    #pragma unroll
    for (int o = 16; o; o >>= 1)
        ex += __shfl_xor_sync(FULLMASK, ex, o);
    if (lane == 0)
        out[b] = (mm + lg2_(ex)) * LN2;
}

extern "C" void kernel_launch(void* const* d_in, const int* in_sizes, int n_in,
                              void* d_out, int out_size)
{
    const float* em = (const float*)d_in[0];
    const float* tr = (const float*)d_in[1];
    long long em_elems = in_sizes[0];
    if (n_in >= 2 && in_sizes[0] == NTAGS * NTAGS && in_sizes[1] > NTAGS * NTAGS) {
        em = (const float*)d_in[1];
        tr = (const float*)d_in[0];
        em_elems = in_sizes[1];
    }

    int B = out_size;
    int T = (int)(em_elems / ((long long)B * NTAGS));

    int blocks = (B + 1) / 2;  // 2 warps (2 sequences) per 64-thread CTA
    crf_forward_kernel<<<blocks, 64>>>(em, tr, (float*)d_out, B, T);
}

// round 3
// speedup vs baseline: 1.0511x; 1.0511x over previous
#include <cuda_runtime.h>

#define FULLMASK 0xffffffffu
#define NTAGS 32
#define BOS_IDX 30
#define EOS_IDX 31
#define L2E 1.4426950408889634f
#define LN2 0.6931471805599453f

typedef unsigned long long ull;

static __device__ __forceinline__ void ffma2(ull& d, ull a, ull b) {
    asm("fma.rn.f32x2 %0, %1, %2, %0;" : "+l"(d) : "l"(a), "l"(b));
}
static __device__ __forceinline__ ull add2(ull a, ull b) {
    ull r;
    asm("add.rn.f32x2 %0, %1, %2;" : "=l"(r) : "l"(a), "l"(b));
    return r;
}
static __device__ __forceinline__ float ex2_(float x) {
    float r; asm("ex2.approx.f32 %0, %1;" : "=f"(r) : "f"(x)); return r;
}
static __device__ __forceinline__ float lg2_(float x) {
    float r; asm("lg2.approx.f32 %0, %1;" : "=f"(r) : "f"(x)); return r;
}

// s = sum_i E[lane,i] * beta[i], betas read from smem as aligned 64-bit pairs
// (ld.shared.v2.u64 -> register quads feed fma.rn.f32x2 directly, zero MOVs).
static __device__ __forceinline__ float matvec32(const ull* er, unsigned saddr) {
    ull A = 0ull, B = 0ull, C = 0ull, D = 0ull;
    #pragma unroll
    for (int q = 0; q < 4; q++) {
        ull p0, p1, p2, p3;
        asm volatile("ld.shared.v2.u64 {%0,%1}, [%2];"
                     : "=l"(p0), "=l"(p1) : "r"(saddr + q * 32));
        asm volatile("ld.shared.v2.u64 {%0,%1}, [%2];"
                     : "=l"(p2), "=l"(p3) : "r"(saddr + q * 32 + 16));
        ffma2(A, er[4 * q + 0], p0);
        ffma2(B, er[4 * q + 1], p1);
        ffma2(C, er[4 * q + 2], p2);
        ffma2(D, er[4 * q + 3], p3);
    }
    ull S = add2(add2(A, B), add2(C, D));
    float x, y;
    asm("mov.b64 {%0,%1}, %2;" : "=f"(x), "=f"(y) : "l"(S));
    return x + y;
}

// One warp handles TWO sequences (ILP=2 to hide the serial chain), lane = tag.
// Log2-domain additive recurrence (verified numerics):
//   m = a[EOS];  beta = exp2(a - m);  s = E . beta;  a' = em*log2e + m + log2(s)
__global__ __launch_bounds__(128, 1) void crf_forward_kernel(
    const float* __restrict__ emission,   // [B, T, 32]
    const float* __restrict__ trans,      // [32, 32]
    float* __restrict__ out,              // [B]
    int B, int T)
{
    const int lane = threadIdx.x & 31;
    const int w    = threadIdx.x >> 5;
    const int b0   = (blockIdx.x * 4 + w) * 2;   // this warp's first sequence

    __shared__ __align__(16) float sb[4][2][2][NTAGS]; // [warp][buf][seq][tag]

    if (b0 >= B) return;  // warp-uniform

    // one-time: E row for this lane (exp of transitions), packed f32x2 pairs
    ull er[16];
    {
        const float* trow = trans + lane * NTAGS;
        #pragma unroll
        for (int q = 0; q < 16; q++) {
            float x = expf(trow[2 * q]);      // exp(-1000) -> 0 for BOS row
            float y = expf(trow[2 * q + 1]);
            asm("mov.b64 %0, {%1,%2};" : "=l"(er[q]) : "f"(x), "f"(y));
        }
    }

    const float* em0 = emission + (size_t)b0 * T * NTAGS + lane;
    const float* em1 = em0 + (size_t)T * NTAGS;

    // step 0 analytic (only BOS survives init alpha), in log2 units
    float tb = trans[lane * NTAGS + BOS_IDX];
    float a0 = (em0[0] + tb) * L2E;
    float a1 = (em1[0] + tb) * L2E;

    // emission prefetch rings, depth 4 (raw values; log2e folded at use)
    float p0[4], p1[4];
    #pragma unroll
    for (int i = 0; i < 4; i++) {
        int tt = (i + 1 < T) ? (i + 1) : (T - 1);
        p0[i] = em0[(size_t)tt * NTAGS];
        p1[i] = em1[(size_t)tt * NTAGS];
    }

    const unsigned sa = (unsigned)__cvta_generic_to_shared(&sb[w][0][0][0]);

    #pragma unroll 4
    for (int t = 1; t < T; ++t) {
        float e0 = p0[0], e1 = p1[0];
        p0[0] = p0[1]; p0[1] = p0[2]; p0[2] = p0[3];
        p1[0] = p1[1]; p1[1] = p1[2]; p1[2] = p1[3];
        int tp = (t + 4 < T) ? (t + 4) : (T - 1);
        p0[3] = em0[(size_t)tp * NTAGS];
        p1[3] = em1[(size_t)tp * NTAGS];

        float m0 = __shfl_sync(FULLMASK, a0, EOS_IDX);
        float m1 = __shfl_sync(FULLMASK, a1, EOS_IDX);
        float be0 = ex2_(a0 - m0);            // exp2(-inf)=0 on dead BOS lane
        float be1 = ex2_(a1 - m1);

        unsigned base = sa + (t & 1) * (2 * NTAGS * 4);
        asm volatile("st.shared.f32 [%0], %1;" :: "r"(base + lane * 4), "f"(be0) : "memory");
        asm volatile("st.shared.f32 [%0], %1;" :: "r"(base + NTAGS * 4 + lane * 4), "f"(be1) : "memory");
        __syncwarp();

        float s0 = matvec32(er, base);
        float s1 = matvec32(er, base + NTAGS * 4);

        a0 = fmaf(e0, L2E, m0 + lg2_(s0));    // log2(0) = -inf on BOS lane: ok
        a1 = fmaf(e1, L2E, m1 + lg2_(s1));
    }

    // terminal: lse(alpha + trans[EOS,:]) per sequence, over the warp
    float te = trans[EOS_IDX * NTAGS + lane] * L2E;
    #pragma unroll
    for (int s = 0; s < 2; s++) {
        float v = (s == 0 ? a0 : a1) + te;
        float mm = v;
        #pragma unroll
        for (int o = 16; o; o >>= 1)
            mm = fmaxf(mm, __shfl_xor_sync(FULLMASK, mm, o));
        float ex = ex2_(v - mm);
        #pragma unroll
        for (int o = 16; o; o >>= 1)
            ex += __shfl_xor_sync(FULLMASK, ex, o);
        if (lane == 0)
            out[b0 + s] = (mm + lg2_(ex)) * LN2;
    }
}

extern "C" void kernel_launch(void* const* d_in, const int* in_sizes, int n_in,
                              void* d_out, int out_size)
{
    const float* em = (const float*)d_in[0];
    const float* tr = (const float*)d_in[1];
    long long em_elems = in_sizes[0];
    if (n_in >= 2 && in_sizes[0] == NTAGS * NTAGS && in_sizes[1] > NTAGS * NTAGS) {
        em = (const float*)d_in[1];
        tr = (const float*)d_in[0];
        em_elems = in_sizes[1];
    }

    int B = out_size;
    int T = (int)(em_elems / ((long long)B * NTAGS));

    // 128 threads = 4 warps/CTA, 2 sequences per warp -> 8 sequences per CTA
    int blocks = (B + 7) / 8;
    crf_forward_kernel<<<blocks, 128>>>(em, tr, (float*)d_out, B, T);
}

// round 4
// speedup vs baseline: 1.7595x; 1.6740x over previous
#include <cuda_runtime.h>

#define FULLMASK 0xffffffffu
#define NTAGS 32
#define BOS_IDX 30
#define EOS_IDX 31
#define L2E 1.4426950408889634f
#define LN2 0.6931471805599453f

typedef unsigned long long ull;

static __device__ __forceinline__ void ffma2(ull& d, ull a, ull b) {
    asm("fma.rn.f32x2 %0, %1, %2, %0;" : "+l"(d) : "l"(a), "l"(b));
}
static __device__ __forceinline__ ull add2(ull a, ull b) {
    ull r;
    asm("add.rn.f32x2 %0, %1, %2;" : "=l"(r) : "l"(a), "l"(b));
    return r;
}
static __device__ __forceinline__ float ex2_(float x) {
    float r; asm("ex2.approx.f32 %0, %1;" : "=f"(r) : "f"(x)); return r;
}
static __device__ __forceinline__ float lg2_(float x) {
    float r; asm("lg2.approx.f32 %0, %1;" : "=f"(r) : "f"(x)); return r;
}

// One warp per sequence, lane = tag. Multiplicative lag-1 recurrence:
//   s_j   = sum_i G[j,i] * beta_i          (G = exp(transitions), in regs)
//   beta' = s * K,  K = ex2(em*L2E - D),   D = lg2(s_EOS of previous step)
//   Csum += D; alpha materialized once at the end as lg2(beta)+Csum.
// On the serial chain per step: FMUL, STS, syncwarp, LDS.128 x8, FFMA2 tree.
// lg2/ex2/shfl all have one full step of slack (lag-1).
__global__ __launch_bounds__(64, 1) void crf_forward_kernel(
    const float* __restrict__ emission,   // [B, T, 32]
    const float* __restrict__ trans,      // [32, 32]
    float* __restrict__ out,              // [B]
    int B, int T)
{
    const int lane = threadIdx.x & 31;
    const int w    = threadIdx.x >> 5;
    const int b    = blockIdx.x * 2 + w;

    __shared__ __align__(16) float sb[2][2][NTAGS];  // [warp][buf][tag]

    if (b >= B) return;  // warp-uniform

    // one-time: G row for this lane (exp of transitions), packed f32x2
    ull er[16];
    {
        const float* trow = trans + lane * NTAGS;
        #pragma unroll
        for (int q = 0; q < 16; q++) {
            float x = expf(trow[2 * q]);     // exp(-1000) -> 0 for BOS row
            float y = expf(trow[2 * q + 1]);
            asm("mov.b64 %0, {%1,%2};" : "=l"(er[q]) : "f"(x), "f"(y));
        }
    }

    const float* em = emission + (size_t)b * T * NTAGS + lane;

    // step 0 analytic (only BOS survives init alpha), log2 units, EOS-anchored
    float a2 = (em[0] + trans[lane * NTAGS + BOS_IDX]) * L2E;
    float Csum = __shfl_sync(FULLMASK, a2, EOS_IDX);
    float beta = ex2_(a2 - Csum);            // 0 on dead BOS lane
    float sEOSp = 1.0f;                      // => D = 0 on first iteration

    // emission prefetch ring, depth 6
    float ring[6];
    #pragma unroll
    for (int i = 0; i < 6; i++) {
        int tt = (i + 1 < T) ? (i + 1) : (T - 1);
        ring[i] = em[(size_t)tt * NTAGS];
    }

    const unsigned sa =
        (unsigned)__cvta_generic_to_shared(&sb[w][0][0]);

    #pragma unroll 6
    for (int t = 1; t < T; ++t) {
        float emv = ring[0];
        ring[0] = ring[1]; ring[1] = ring[2]; ring[2] = ring[3];
        ring[3] = ring[4]; ring[4] = ring[5];
        int tp = (t + 6 < T) ? (t + 6) : (T - 1);
        ring[5] = em[(size_t)tp * NTAGS];

        // off-chain (lag-1): rescale constant from previous step's s_EOS
        float D = lg2_(sEOSp);
        Csum += D;
        float K = ex2_(fmaf(emv, L2E, -D));

        unsigned base = sa + (t & 1) * (NTAGS * 4);
        asm volatile("st.shared.f32 [%0], %1;"
                     :: "r"(base + lane * 4), "f"(beta) : "memory");
        __syncwarp();

        // s_j = sum_i G[j,i] * beta_i : 8x LDS.128 -> 16x FFMA2, 4 accums
        ull A = 0ull, Bc = 0ull, C = 0ull, Dc = 0ull;
        #pragma unroll
        for (int q = 0; q < 4; q++) {
            ull p0, p1, p2, p3;
            asm volatile("ld.shared.v2.u64 {%0,%1}, [%2];"
                         : "=l"(p0), "=l"(p1) : "r"(base + q * 32));
            asm volatile("ld.shared.v2.u64 {%0,%1}, [%2];"
                         : "=l"(p2), "=l"(p3) : "r"(base + q * 32 + 16));
            ffma2(A,  er[4 * q + 0], p0);
            ffma2(Bc, er[4 * q + 1], p1);
            ffma2(C,  er[4 * q + 2], p2);
            ffma2(Dc, er[4 * q + 3], p3);
        }
        ull S = add2(add2(A, Bc), add2(C, Dc));
        float sx, sy;
        asm("mov.b64 {%0,%1}, %2;" : "=f"(sx), "=f"(sy) : "l"(S));
        float s = sx + sy;

        sEOSp = __shfl_sync(FULLMASK, s, EOS_IDX);  // consumed next iter
        beta = s * K;                               // only on-chain math
    }

    // materialize alpha (log2 units) and terminal lse over the warp
    float ahat = lg2_(beta) + Csum;                 // -inf on BOS lane: ok
    float v = fmaf(trans[EOS_IDX * NTAGS + lane], L2E, ahat);
    float mm = v;
    #pragma unroll
    for (int o = 16; o; o >>= 1)
        mm = fmaxf(mm, __shfl_xor_sync(FULLMASK, mm, o));
    float ex = ex2_(v - mm);
    #pragma unroll
    for (int o = 16; o; o >>= 1)
        ex += __shfl_xor_sync(FULLMASK, ex, o);
    if (lane == 0)
        out[b] = (mm + lg2_(ex)) * LN2;
}

extern "C" void kernel_launch(void* const* d_in, const int* in_sizes, int n_in,
                              void* d_out, int out_size)
{
    const float* em = (const float*)d_in[0];
    const float* tr = (const float*)d_in[1];
    long long em_elems = in_sizes[0];
    if (n_in >= 2 && in_sizes[0] == NTAGS * NTAGS && in_sizes[1] > NTAGS * NTAGS) {
        em = (const float*)d_in[1];
        tr = (const float*)d_in[0];
        em_elems = in_sizes[1];
    }

    int B = out_size;
    int T = (int)(em_elems / ((long long)B * NTAGS));

    int blocks = (B + 1) / 2;  // 2 warps (2 sequences) per 64-thread CTA
    crf_forward_kernel<<<blocks, 64>>>(em, tr, (float*)d_out, B, T);
}